// round 9
// baseline (speedup 1.0000x reference)
#include <cuda_runtime.h>
#include <cuda_fp16.h>
#include <cstdint>

// Problem shape (fixed per metadata):
//   X0 [4,1024,256] f32, t [4,1] f32, Wc_w [128,256] f32, Wc_b [128] f32,
//   w [128] f32, A [64,128,6] f32, Bp [64,128,6] f32  ->  out [4,1024,64] f32
#define B_   4
#define S_   1024
#define ROWS 4096        // B_*S_
#define DIN  256
#define Q_   128
#define KF   6
#define DOUT 64
#define KSL  1536        // GEMM2: 1 fp16 slot per feature
#define WPL  512         // GEMM1 B: 2 planes (wh | wl) of 256 slots

// Scratch (no device allocs allowed)
__device__ __half g_bh[DOUT * KSL];            // 192 KB  [d][k] fp16 coeffs
__device__ __half g_wsp[Q_ * WPL];             // 128 KB  [q][wh(256)|wl(256)]

// ---------------------------------------------------------------------------
// m16n8k16 fp16 MMA, fp32 accumulate + ldmatrix helpers
// ---------------------------------------------------------------------------
__device__ __forceinline__ void mma16816(float* c, const uint32_t* a,
                                         const uint32_t* b) {
    asm volatile(
        "mma.sync.aligned.m16n8k16.row.col.f32.f16.f16.f32 "
        "{%0,%1,%2,%3}, {%4,%5,%6,%7}, {%8,%9}, {%0,%1,%2,%3};"
        : "+f"(c[0]), "+f"(c[1]), "+f"(c[2]), "+f"(c[3])
        : "r"(a[0]), "r"(a[1]), "r"(a[2]), "r"(a[3]), "r"(b[0]), "r"(b[1]));
}
__device__ __forceinline__ void ldsm_x4(uint32_t* r, uint32_t addr) {
    asm volatile("ldmatrix.sync.aligned.m8n8.x4.shared.b16 {%0,%1,%2,%3}, [%4];"
                 : "=r"(r[0]), "=r"(r[1]), "=r"(r[2]), "=r"(r[3]) : "r"(addr));
}
__device__ __forceinline__ uint32_t smem_u32(const void* p) {
    uint32_t a;
    asm("{ .reg .u64 t; cvta.to.shared.u64 t, %1; cvt.u32.u64 %0, t; }"
        : "=r"(a) : "l"(p));
    return a;
}

// ---------------------------------------------------------------------------
// Kernel 1 (prep): fold A,Bp -> g_bh; split W -> wh/wl planes.
// ---------------------------------------------------------------------------
__global__ void prep_kernel(const float* __restrict__ A, const float* __restrict__ Bp,
                            const float* __restrict__ W) {
    int i = blockIdx.x * blockDim.x + threadIdx.x;       // 0 .. 24575
    {   // g_bh: items 2i, 2i+1  (49152 total)
        int idx = 2 * i;
        int d   = idx / (Q_ * KF);
        int rem = idx - d * (Q_ * KF);                   // even
        float2 a2 = *(const float2*)&A[idx];
        float2 b2 = *(const float2*)&Bp[idx];
        float s0, c0, s1, c1;
        __sincosf(b2.x, &s0, &c0);
        __sincosf(b2.y, &s1, &c1);
        __half2 h0 = __floats2half2_rn(a2.x * c0, a2.x * s0);
        __half2 h1 = __floats2half2_rn(a2.y * c1, a2.y * s1);
        *(uint2*)&g_bh[d * KSL + rem * 2] =
            make_uint2(*(uint32_t*)&h0, *(uint32_t*)&h1);
    }
    if (i < (Q_ * DIN) / 2) {                            // W: items 2i, 2i+1
        int idx = 2 * i;
        int q = idx >> 8, k = idx & 255;                 // k even
        float2 w2 = *(const float2*)&W[idx];
        __half wh0 = __float2half_rn(w2.x);
        __half wl0 = __float2half_rn(w2.x - __half2float(wh0));
        __half wh1 = __float2half_rn(w2.y);
        __half wl1 = __float2half_rn(w2.y - __half2float(wh1));
        __half2 hp = __halves2half2(wh0, wh1);
        __half2 lp = __halves2half2(wl0, wl1);
        *(uint32_t*)&g_wsp[q * WPL + k]       = *(uint32_t*)&hp;
        *(uint32_t*)&g_wsp[q * WPL + 256 + k] = *(uint32_t*)&lp;
    }
}

// ---------------------------------------------------------------------------
// Kernel 2 (mega): GEMM1 -> ANG smem -> featgen -> GEMM2.
// 128 CTAs x 256 threads (8 warps = 2 row-groups x 4 col-groups), 32 rows/CTA.
// Pipeline: ONE barrier per chunk. A tiles double-buffered in smem (LDSM
// fragment loads); B fragments (W / coeffs) live ONLY in registers, loaded
// directly from global one chunk ahead (same addrs across CTAs -> L2 bcast).
// smem (static, 30208 B):
//   [0,16896)      ANG  : angle tile f32 [q][33]
//   [16896,26112)  Ax1  : phase-1 A double buffer, 2 x [32][72] halves
//   [16896,30208)  As2  : phase-2 A double buffer, 2 x [32][104] halves
//   (Ax1/As2 overlap in space, disjoint in time)
// ---------------------------------------------------------------------------
#define KP1 72
#define KP2 104
#define SM_BYTES 30208
#define OFF_AX1 16896
#define AX1_SZ  4608
#define OFF_AS2 16896
#define AS2_SZ  6656

__global__ __launch_bounds__(256) void mega_kernel(
    const float* __restrict__ X0, const float* __restrict__ bias,
    const float* __restrict__ wvec, const float* __restrict__ tvec,
    float* __restrict__ out)
{
    __shared__ __align__(16) char sm[SM_BYTES];
    float* ANG = (float*)sm;                       // [q*33 + row]

    int tid  = threadIdx.x;
    int lane = tid & 31;
    int w    = tid >> 5;              // warp 0..7
    int r0   = blockIdx.x * 32;
    int ra   = lane >> 2;
    int cc   = 2 * (lane & 3);
    // ldmatrix lane->row/col mapping (x4: m0..m3 = [rows0-7|rows8-15] x [c0-7|c8-15])
    int lrow = (lane & 7) + ((lane >> 3) & 1) * 8;
    int lcol = (lane >> 4) * 8;

    uint32_t ax1b[2] = { smem_u32(sm + OFF_AX1), smem_u32(sm + OFF_AX1 + AX1_SZ) };
    uint32_t as2b[2] = { smem_u32(sm + OFF_AS2), smem_u32(sm + OFF_AS2 + AS2_SZ) };

    // ======================= PHASE 1: angle GEMM =======================
    {
        int wr = w >> 2;              // rows wr*16 .. +15
        int wq = w & 3;               // q    wq*32 .. +31
        float acc[4][4] = {};

        int xrow = tid >> 3;          // A staging row 0..31
        int kgrp = (tid & 7) * 4;     // f32 k offset (4 floats/thread)
        uint32_t a1off = (uint32_t)(((wr * 16 + lrow) * KP1 + lcol) * 2);

        // B fragments in registers: [kt][n][{h0,h1,l0,l1}]
        uint32_t Wf[2][4][4];
        auto LDW = [&](int c) {
            #pragma unroll
            for (int kt = 0; kt < 2; kt++)
                #pragma unroll
                for (int n = 0; n < 4; n++) {
                    const __half* bp = &g_wsp[(wq * 32 + n * 8 + ra) * WPL
                                              + c * 32 + kt * 16 + cc];
                    Wf[kt][n][0] = *(const uint32_t*)(bp);
                    Wf[kt][n][1] = *(const uint32_t*)(bp + 8);
                    Wf[kt][n][2] = *(const uint32_t*)(bp + 256);
                    Wf[kt][n][3] = *(const uint32_t*)(bp + 264);
                }
        };
        // A staging: split 4 f32 -> xh @ col kgrp, xl @ col 32+kgrp
        auto stageA = [&](const float4& nx, int buf) {
            float xf[4] = {nx.x, nx.y, nx.z, nx.w};
            uint32_t ph[2], pl[2];
            #pragma unroll
            for (int j = 0; j < 2; j++) {
                float a0 = xf[2 * j], a1 = xf[2 * j + 1];
                __half h0 = __float2half_rn(a0);
                __half l0 = __float2half_rn(a0 - __half2float(h0));
                __half h1 = __float2half_rn(a1);
                __half l1 = __float2half_rn(a1 - __half2float(h1));
                __half2 hh = __halves2half2(h0, h1);
                __half2 ll = __halves2half2(l0, l1);
                ph[j] = *(uint32_t*)&hh;
                pl[j] = *(uint32_t*)&ll;
            }
            __half* base = (__half*)(sm + OFF_AX1 + buf * AX1_SZ);
            *(uint2*)&base[xrow * KP1 + kgrp]      = make_uint2(ph[0], ph[1]);
            *(uint2*)&base[xrow * KP1 + 32 + kgrp] = make_uint2(pl[0], pl[1]);
        };

        // prologue
        float4 nx = *(const float4*)&X0[(r0 + xrow) * DIN + kgrp];
        LDW(0);
        stageA(nx, 0);
        nx = *(const float4*)&X0[(r0 + xrow) * DIN + 32 + kgrp];
        __syncthreads();

        for (int c = 0; c < 8; c++) {
            if (c < 7) stageA(nx, (c + 1) & 1);
            // MMA(c): 2 ktiles x {xh*wh, xh*wl, xl*wh} x 4n
            #pragma unroll
            for (int kt = 0; kt < 2; kt++) {
                uint32_t Ah[4], Al[4];
                ldsm_x4(Ah, ax1b[c & 1] + a1off + kt * 32);
                ldsm_x4(Al, ax1b[c & 1] + a1off + kt * 32 + 64);
                #pragma unroll
                for (int n = 0; n < 4; n++) {
                    mma16816(acc[n], Ah, &Wf[kt][n][0]);   // xh*wh
                    mma16816(acc[n], Ah, &Wf[kt][n][2]);   // xh*wl
                    mma16816(acc[n], Al, &Wf[kt][n][0]);   // xl*wh
                }
            }
            if (c < 7) {
                LDW(c + 1);
                if (c < 6)
                    nx = *(const float4*)&X0[(r0 + xrow) * DIN + (c + 2) * 32 + kgrp];
            }
            __syncthreads();
        }

        // epilogue: + bias + w*t -> ANG smem [q][33]  (Ax1 space now dead)
        float tb = tvec[r0 >> 10];
        #pragma unroll
        for (int n = 0; n < 4; n++) {
            int q  = (w & 3) * 32 + n * 8 + cc;
            int rr = wr * 16 + ra;
            float b0 = __ldg(&bias[q])     + __ldg(&wvec[q]) * tb;
            float b1 = __ldg(&bias[q + 1]) + __ldg(&wvec[q + 1]) * tb;
            ANG[q * 33 + rr]           = acc[n][0] + b0;
            ANG[(q + 1) * 33 + rr]     = acc[n][1] + b1;
            ANG[q * 33 + rr + 8]       = acc[n][2] + b0;
            ANG[(q + 1) * 33 + rr + 8] = acc[n][3] + b1;
        }
    }
    __syncthreads();

    // ================= PHASE 2: featgen + GEMM2 =================
    {
        int wr2 = w >> 2;             // rows wr2*16 ..
        int wd  = w & 3;              // d    wd*16 .. +15
        float acc[2][4] = {};

        int row = tid & 31;           // featgen row
        int ql  = tid >> 5;           // featgen local q (0..7)
        uint32_t a2off = (uint32_t)(((wr2 * 16 + lrow) * KP2 + lcol) * 2);

        // B fragments in registers: [kt][nt][pair]
        uint32_t Bf[6][2][2];
        auto LDB = [&](int c) {
            #pragma unroll
            for (int kt = 0; kt < 6; kt++)
                #pragma unroll
                for (int nt = 0; nt < 2; nt++) {
                    const __half* bp = &g_bh[(wd * 16 + nt * 8 + ra) * KSL
                                             + c * 96 + kt * 16 + cc];
                    Bf[kt][nt][0] = *(const uint32_t*)(bp);
                    Bf[kt][nt][1] = *(const uint32_t*)(bp + 8);
                }
        };
        auto featgen = [&](int c, int buf) {
            float a = ANG[(c * 8 + ql) * 33 + row];
            // Cody-Waite reduction mod 2*pi (C1=6.28125: 9 mantissa bits)
            float n = rintf(a * 0.15915494309189535f);
            float rr = fmaf(n, -6.28125f, a);
            rr = fmaf(n, -1.9353071795864769e-3f, rr);
            float s1, c1;
            __sincosf(rr, &s1, &c1);
            float f[12];
            f[0] = s1; f[1] = c1;
            float sk = s1, ck = c1;
            #pragma unroll
            for (int h = 1; h < KF; h++) {
                float sn = fmaf(sk, c1, ck * s1);
                float cn = fmaf(ck, c1, -sk * s1);
                f[2 * h] = sn; f[2 * h + 1] = cn;
                sk = sn; ck = cn;
            }
            uint32_t hv[6];
            #pragma unroll
            for (int g = 0; g < 6; g++) {
                __half2 h2 = __floats2half2_rn(f[2 * g], f[2 * g + 1]);
                hv[g] = *(uint32_t*)&h2;
            }
            __half* base = (__half*)(sm + OFF_AS2 + buf * AS2_SZ);
            uint64_t* dst = (uint64_t*)&base[row * KP2 + ql * 12];
            dst[0] = (uint64_t)hv[0] | ((uint64_t)hv[1] << 32);
            dst[1] = (uint64_t)hv[2] | ((uint64_t)hv[3] << 32);
            dst[2] = (uint64_t)hv[4] | ((uint64_t)hv[5] << 32);
        };

        // prologue
        LDB(0);
        featgen(0, 0);
        __syncthreads();

        for (int c = 0; c < 16; c++) {
            if (c < 15) featgen(c + 1, (c + 1) & 1);
            // MMA(c): 6 ktiles x 2n
            #pragma unroll
            for (int kt = 0; kt < 6; kt++) {
                uint32_t Af[4];
                ldsm_x4(Af, as2b[c & 1] + a2off + kt * 32);
                #pragma unroll
                for (int nt = 0; nt < 2; nt++)
                    mma16816(acc[nt], Af, &Bf[kt][nt][0]);
            }
            if (c < 15) LDB(c + 1);
            __syncthreads();
        }

        // output epilogue
        int orow = r0 + wr2 * 16 + ra;
        #pragma unroll
        for (int nt = 0; nt < 2; nt++) {
            int ccg = wd * 16 + nt * 8 + cc;
            *(float2*)&out[orow * DOUT + ccg]       = make_float2(acc[nt][0], acc[nt][1]);
            *(float2*)&out[(orow + 8) * DOUT + ccg] = make_float2(acc[nt][2], acc[nt][3]);
        }
    }
}

// ---------------------------------------------------------------------------
extern "C" void kernel_launch(void* const* d_in, const int* in_sizes, int n_in,
                              void* d_out, int out_size) {
    const float* X0   = (const float*)d_in[0];
    const float* tvec = (const float*)d_in[1];
    const float* Wc_w = (const float*)d_in[2];
    const float* Wc_b = (const float*)d_in[3];
    const float* wvec = (const float*)d_in[4];
    const float* A    = (const float*)d_in[5];
    const float* Bp   = (const float*)d_in[6];
    float* out = (float*)d_out;

    prep_kernel<<<96, 256>>>(A, Bp, Wc_w);
    mega_kernel<<<ROWS / 32, 256>>>(X0, Wc_b, wvec, tvec, out);
}

// round 10
// speedup vs baseline: 1.3802x; 1.3802x over previous
#include <cuda_runtime.h>
#include <cuda_fp16.h>
#include <cstdint>

// Problem shape (fixed per metadata):
//   X0 [4,1024,256] f32, t [4,1] f32, Wc_w [128,256] f32, Wc_b [128] f32,
//   w [128] f32, A [64,128,6] f32, Bp [64,128,6] f32  ->  out [4,1024,64] f32
#define B_   4
#define S_   1024
#define ROWS 4096        // B_*S_
#define DIN  256
#define Q_   128
#define KF   6
#define DOUT 64
#define KSL  1536        // GEMM2: 1 fp16 slot per feature

// Scratch (no device allocs allowed)
__device__ float  g_angle[ROWS * Q_];          // 2 MB
__device__ __half g_bh[DOUT * KSL];            // 192 KB  [d][k] fp16 coeffs

// ---------------------------------------------------------------------------
// m16n8k16 fp16 MMA, fp32 accumulate
// ---------------------------------------------------------------------------
__device__ __forceinline__ void mma16816(float* c, const uint32_t* a,
                                         const uint32_t* b) {
    asm volatile(
        "mma.sync.aligned.m16n8k16.row.col.f32.f16.f16.f32 "
        "{%0,%1,%2,%3}, {%4,%5,%6,%7}, {%8,%9}, {%0,%1,%2,%3};"
        : "+f"(c[0]), "+f"(c[1]), "+f"(c[2]), "+f"(c[3])
        : "r"(a[0]), "r"(a[1]), "r"(a[2]), "r"(a[3]), "r"(b[0]), "r"(b[1]));
}

// ---------------------------------------------------------------------------
// Kernel 1: angle GEMM with INLINE W split (no prep kernel).
// 128 CTAs x 128 threads, 32 rows/CTA, K=256 f32 in 8 chunks of 32.
// A slots [xh|xl] (cols 0-31 | 32-63), B slots [wh|wl]; products
// xh*wh + xh*wl + xl*wh (xl*wl dropped, <=2^-22 rel).
// Tail: each CTA computes a 384-element slice of g_bh (A,Bp fold).
// smem: Ws1[128][72] + Ax1[32][72] halves = 23 KB, KP1=72 ->
// fragment LDS banks (4*ra + cc') all-distinct: conflict-free.
// ---------------------------------------------------------------------------
#define KP1 72

__global__ __launch_bounds__(128) void angle_kernel(
    const float* __restrict__ X0, const float* __restrict__ W,
    const float* __restrict__ bias, const float* __restrict__ wvec,
    const float* __restrict__ tvec,
    const float* __restrict__ A, const float* __restrict__ Bp)
{
    __shared__ __align__(16) __half Ws1[Q_][KP1];   // 18 KB
    __shared__ __align__(16) __half Ax1[32][KP1];   //  4.6 KB

    int tid  = threadIdx.x;
    int lane = tid & 31;
    int w    = tid >> 5;              // warp 0..3, q range w*32 .. +31
    int r0   = blockIdx.x * 32;
    int ra   = lane >> 2;
    int cc   = 2 * (lane & 3);

    float acc[2][4][4] = {};          // [mtile][ntile][frag]
    int xrow = tid >> 2;              // A staging row 0..31
    int kgrp = (tid & 3) * 8;         // f32 k offset (8 floats/thread)

    // prologue prefetch chunk 0: X rows + raw W row (q = tid, 32 f32)
    float4 nx0 = *(const float4*)&X0[(r0 + xrow) * DIN + kgrp];
    float4 nx1 = *(const float4*)&X0[(r0 + xrow) * DIN + kgrp + 4];
    float4 nwf[8];
    #pragma unroll
    for (int j = 0; j < 8; j++)
        nwf[j] = *(const float4*)&W[tid * DIN + j * 4];

    for (int c = 0; c < 8; c++) {
        // ---- stage A: split 8 f32 -> xh @ col kgrp, xl @ col 32+kgrp ----
        {
            float xf[8] = {nx0.x, nx0.y, nx0.z, nx0.w,
                           nx1.x, nx1.y, nx1.z, nx1.w};
            uint32_t ph[4], pl[4];
            #pragma unroll
            for (int j = 0; j < 4; j++) {
                float a0 = xf[2 * j], a1 = xf[2 * j + 1];
                __half h0 = __float2half_rn(a0);
                __half l0 = __float2half_rn(a0 - __half2float(h0));
                __half h1 = __float2half_rn(a1);
                __half l1 = __float2half_rn(a1 - __half2float(h1));
                __half2 hh = __halves2half2(h0, h1);
                __half2 ll = __halves2half2(l0, l1);
                ph[j] = *(uint32_t*)&hh;
                pl[j] = *(uint32_t*)&ll;
            }
            *(uint4*)&Ax1[xrow][kgrp]      = make_uint4(ph[0], ph[1], ph[2], ph[3]);
            *(uint4*)&Ax1[xrow][32 + kgrp] = make_uint4(pl[0], pl[1], pl[2], pl[3]);
        }
        // ---- stage B: inline split of 32 f32 -> wh cols 0-31, wl 32-63 ----
        {
            const float* wf = (const float*)nwf;
            uint32_t whp[16], wlp[16];
            #pragma unroll
            for (int j = 0; j < 16; j++) {
                float a0 = wf[2 * j], a1 = wf[2 * j + 1];
                __half h0 = __float2half_rn(a0);
                __half l0 = __float2half_rn(a0 - __half2float(h0));
                __half h1 = __float2half_rn(a1);
                __half l1 = __float2half_rn(a1 - __half2float(h1));
                __half2 hh = __halves2half2(h0, h1);
                __half2 ll = __halves2half2(l0, l1);
                whp[j] = *(uint32_t*)&hh;
                wlp[j] = *(uint32_t*)&ll;
            }
            #pragma unroll
            for (int g = 0; g < 4; g++) {
                *(uint4*)&Ws1[tid][g * 8] =
                    make_uint4(whp[4*g], whp[4*g+1], whp[4*g+2], whp[4*g+3]);
                *(uint4*)&Ws1[tid][32 + g * 8] =
                    make_uint4(wlp[4*g], wlp[4*g+1], wlp[4*g+2], wlp[4*g+3]);
            }
        }
        __syncthreads();

        // ---- prefetch next chunk (hidden under MMA) ----
        if (c < 7) {
            nx0 = *(const float4*)&X0[(r0 + xrow) * DIN + (c + 1) * 32 + kgrp];
            nx1 = *(const float4*)&X0[(r0 + xrow) * DIN + (c + 1) * 32 + kgrp + 4];
            #pragma unroll
            for (int j = 0; j < 8; j++)
                nwf[j] = *(const float4*)&W[tid * DIN + (c + 1) * 32 + j * 4];
        }

        // ---- MMA: 2 ktiles x {xh*wh, xh*wl, xl*wh} x 2m x 4n ----
        #pragma unroll
        for (int kt = 0; kt < 2; kt++) {
            int kh = kt * 16 + cc;        // xh / wh cols
            int kl = 32 + kh;             // xl / wl cols
            uint32_t A0h[4], A1h[4], A0l[4], A1l[4];
            A0h[0] = *(const uint32_t*)&Ax1[ra][kh];
            A0h[1] = *(const uint32_t*)&Ax1[ra + 8][kh];
            A0h[2] = *(const uint32_t*)&Ax1[ra][kh + 8];
            A0h[3] = *(const uint32_t*)&Ax1[ra + 8][kh + 8];
            A1h[0] = *(const uint32_t*)&Ax1[ra + 16][kh];
            A1h[1] = *(const uint32_t*)&Ax1[ra + 24][kh];
            A1h[2] = *(const uint32_t*)&Ax1[ra + 16][kh + 8];
            A1h[3] = *(const uint32_t*)&Ax1[ra + 24][kh + 8];
            A0l[0] = *(const uint32_t*)&Ax1[ra][kl];
            A0l[1] = *(const uint32_t*)&Ax1[ra + 8][kl];
            A0l[2] = *(const uint32_t*)&Ax1[ra][kl + 8];
            A0l[3] = *(const uint32_t*)&Ax1[ra + 8][kl + 8];
            A1l[0] = *(const uint32_t*)&Ax1[ra + 16][kl];
            A1l[1] = *(const uint32_t*)&Ax1[ra + 24][kl];
            A1l[2] = *(const uint32_t*)&Ax1[ra + 16][kl + 8];
            A1l[3] = *(const uint32_t*)&Ax1[ra + 24][kl + 8];
            #pragma unroll
            for (int n = 0; n < 4; n++) {
                int q0 = w * 32 + n * 8 + ra;
                uint32_t Bh[2], Bl[2];
                Bh[0] = *(const uint32_t*)&Ws1[q0][kh];
                Bh[1] = *(const uint32_t*)&Ws1[q0][kh + 8];
                Bl[0] = *(const uint32_t*)&Ws1[q0][kl];
                Bl[1] = *(const uint32_t*)&Ws1[q0][kl + 8];
                mma16816(acc[0][n], A0h, Bh);   // xh*wh
                mma16816(acc[1][n], A1h, Bh);
                mma16816(acc[0][n], A0h, Bl);   // xh*wl
                mma16816(acc[1][n], A1h, Bl);
                mma16816(acc[0][n], A0l, Bh);   // xl*wh
                mma16816(acc[1][n], A1l, Bh);
            }
        }
        __syncthreads();
    }

    // ---- epilogue: + bias + w*t -> g_angle ----
    float tb = tvec[r0 >> 10];
    #pragma unroll
    for (int n = 0; n < 4; n++) {
        int q = w * 32 + n * 8 + cc;
        float b0 = __ldg(&bias[q])     + __ldg(&wvec[q]) * tb;
        float b1 = __ldg(&bias[q + 1]) + __ldg(&wvec[q + 1]) * tb;
        #pragma unroll
        for (int m = 0; m < 2; m++) {
            int rr = r0 + m * 16 + ra;
            float* a4 = acc[m][n];
            *(float2*)&g_angle[rr * Q_ + q]       = make_float2(a4[0] + b0, a4[1] + b1);
            *(float2*)&g_angle[(rr + 8) * Q_ + q] = make_float2(a4[2] + b0, a4[3] + b1);
        }
    }

    // ---- tail: this CTA's 384-element slice of the A,Bp fold (g_bh) ----
    //   coeff slot q*12 + 2h : A*cos(Bp) ; slot q*12+2h+1 : A*sin(Bp)
    #pragma unroll
    for (int j = 0; j < 3; j++) {
        int i = blockIdx.x * 384 + j * 128 + tid;     // 0 .. 49151
        int d   = i / (Q_ * KF);
        int rem = i - d * (Q_ * KF);                  // q*6 + h
        float a = A[i], b = Bp[i];
        float sb, cb;
        __sincosf(b, &sb, &cb);
        __half2 hv = __floats2half2_rn(a * cb, a * sb);
        *(uint32_t*)&g_bh[d * KSL + rem * 2] = *(uint32_t*)&hv;
    }
}

// ---------------------------------------------------------------------------
// Kernel 2: fused feature-gen + HMMA GEMM2 (verbatim R5 structure, proven).
// 128 CTAs x 128 threads, 32 rows/CTA. 8 chunks of 16 q (192 k-slots).
// smem stride 400B -> conflict-free fragment LDS/STS.
// ---------------------------------------------------------------------------
#define KPAD   200
#define CHUNK_K 192
#define NCHUNK  8

__global__ __launch_bounds__(128) void fuse_kernel(float* __restrict__ out)
{
    __shared__ __half As[32][KPAD];   // 12.8 KB
    __shared__ __half Bs[64][KPAD];   // 25.6 KB

    int tid  = threadIdx.x;
    int lane = tid & 31;
    int w    = tid >> 5;
    int r0   = blockIdx.x * 32;
    int row  = lane;                  // featgen row
    int qlb  = w * 4;                 // featgen local-q base (4 q per thread)

    float acc[2][2][4] = {};

    // prologue prefetch: chunk 0
    uint4 nB[12];
    #pragma unroll
    for (int r = 0; r < 12; r++) {
        int idx = tid + 128 * r;
        int d   = idx / 24;
        int kc  = idx - d * 24;
        nB[r] = *(const uint4*)&g_bh[d * KSL + kc * 8];
    }
    float4 nAng = *(const float4*)&g_angle[(r0 + row) * Q_ + qlb];

    for (int c = 0; c < NCHUNK; c++) {
        // ---- features for 4 q's -> fp16, STS ----
        {
            float af[4] = {nAng.x, nAng.y, nAng.z, nAng.w};
            #pragma unroll
            for (int p = 0; p < 4; p++) {
                float a = af[p];
                // Cody-Waite reduction mod 2*pi (C1=6.28125: 9 mantissa bits)
                float n = rintf(a * 0.15915494309189535f);
                float rr = fmaf(n, -6.28125f, a);
                rr = fmaf(n, -1.9353071795864769e-3f, rr);
                float s1, c1;
                __sincosf(rr, &s1, &c1);
                float f[12];
                f[0] = s1; f[1] = c1;
                float sk = s1, ck = c1;
                #pragma unroll
                for (int h = 1; h < KF; h++) {
                    float sn = fmaf(sk, c1, ck * s1);
                    float cn = fmaf(ck, c1, -sk * s1);
                    f[2 * h] = sn; f[2 * h + 1] = cn;
                    sk = sn; ck = cn;
                }
                uint32_t hv[6];
                #pragma unroll
                for (int g = 0; g < 6; g++) {
                    __half2 h2 = __floats2half2_rn(f[2 * g], f[2 * g + 1]);
                    hv[g] = *(uint32_t*)&h2;
                }
                int kl = (qlb + p) * 12;
                uint64_t* dst = (uint64_t*)&As[row][kl];
                dst[0] = (uint64_t)hv[0] | ((uint64_t)hv[1] << 32);
                dst[1] = (uint64_t)hv[2] | ((uint64_t)hv[3] << 32);
                dst[2] = (uint64_t)hv[4] | ((uint64_t)hv[5] << 32);
            }
        }
        // ---- stage B chunk ----
        #pragma unroll
        for (int r = 0; r < 12; r++) {
            int idx = tid + 128 * r;
            int d   = idx / 24;
            int kc  = idx - d * 24;
            *(uint4*)&Bs[d][kc * 8] = nB[r];
        }
        __syncthreads();

        // ---- prefetch next chunk ----
        if (c < NCHUNK - 1) {
            #pragma unroll
            for (int r = 0; r < 12; r++) {
                int idx = tid + 128 * r;
                int d   = idx / 24;
                int kc  = idx - d * 24;
                nB[r] = *(const uint4*)&g_bh[d * KSL + (c + 1) * CHUNK_K + kc * 8];
            }
            nAng = *(const float4*)&g_angle[(r0 + row) * Q_ + (c + 1) * 16 + qlb];
        }

        // ---- MMA: 12 ktiles x (2m x 2n) ----
        int ra = lane >> 2;
        int cc = 2 * (lane & 3);
        #pragma unroll
        for (int kt = 0; kt < 12; kt++) {
            int k0 = kt * 16 + cc;
            uint32_t A0[4], A1[4], Bf0[2], Bf1[2];
            A0[0] = *(const uint32_t*)&As[ra][k0];
            A0[1] = *(const uint32_t*)&As[ra + 8][k0];
            A0[2] = *(const uint32_t*)&As[ra][k0 + 8];
            A0[3] = *(const uint32_t*)&As[ra + 8][k0 + 8];
            A1[0] = *(const uint32_t*)&As[ra + 16][k0];
            A1[1] = *(const uint32_t*)&As[ra + 24][k0];
            A1[2] = *(const uint32_t*)&As[ra + 16][k0 + 8];
            A1[3] = *(const uint32_t*)&As[ra + 24][k0 + 8];
            int d0 = w * 16 + ra;
            Bf0[0] = *(const uint32_t*)&Bs[d0][k0];
            Bf0[1] = *(const uint32_t*)&Bs[d0][k0 + 8];
            Bf1[0] = *(const uint32_t*)&Bs[d0 + 8][k0];
            Bf1[1] = *(const uint32_t*)&Bs[d0 + 8][k0 + 8];
            mma16816(acc[0][0], A0, Bf0);
            mma16816(acc[0][1], A0, Bf1);
            mma16816(acc[1][0], A1, Bf0);
            mma16816(acc[1][1], A1, Bf1);
        }
        __syncthreads();
    }

    // ---- epilogue ----
    int orow = r0 + (lane >> 2);
    int ocol = w * 16 + 2 * (lane & 3);
    #pragma unroll
    for (int m = 0; m < 2; m++) {
        #pragma unroll
        for (int nt = 0; nt < 2; nt++) {
            float* a4 = acc[m][nt];
            int rr  = orow + m * 16;
            int ccg = ocol + nt * 8;
            *(float2*)&out[rr * DOUT + ccg]       = make_float2(a4[0], a4[1]);
            *(float2*)&out[(rr + 8) * DOUT + ccg] = make_float2(a4[2], a4[3]);
        }
    }
}

// ---------------------------------------------------------------------------
extern "C" void kernel_launch(void* const* d_in, const int* in_sizes, int n_in,
                              void* d_out, int out_size) {
    const float* X0   = (const float*)d_in[0];
    const float* tvec = (const float*)d_in[1];
    const float* Wc_w = (const float*)d_in[2];
    const float* Wc_b = (const float*)d_in[3];
    const float* wvec = (const float*)d_in[4];
    const float* A    = (const float*)d_in[5];
    const float* Bp   = (const float*)d_in[6];
    float* out = (float*)d_out;

    angle_kernel<<<ROWS / 32, 128>>>(X0, Wc_w, Wc_b, wvec, tvec, A, Bp);
    fuse_kernel<<<ROWS / 32, 128>>>(out);
}